// round 13
// baseline (speedup 1.0000x reference)
#include <cuda_runtime.h>

// ---------------------------------------------------------------------------
// Groupwise CNN + 32 independent 2-layer LSTMs + gaussian head
// ---------------------------------------------------------------------------

typedef unsigned long long ull;

#define B_    128
#define W_    128
#define FC1_  32
#define H_    32

// scratch (allocation-free rule: __device__ globals)
__device__ float g_z[FC1_ * 16384];          // [f][b*128+t]  (transposed for lstm)
__device__ float g_comb[B_ * FC1_ * H_];     // [b][f*32+h]

__device__ __forceinline__ void ffma2(ull &d, ull a, ull b) {
    asm("fma.rn.f32x2 %0, %1, %2, %0;" : "+l"(d) : "l"(a), "l"(b));
}
__device__ __forceinline__ float redu(ull a) {
    float lo, hi;
    asm("mov.b64 {%0,%1}, %2;" : "=f"(lo), "=f"(hi) : "l"(a));
    return lo + hi;
}
__device__ __forceinline__ ull pk2(float lo, float hi) {
    ull r;
    asm("mov.b64 %0, {%1,%2};" : "=l"(r) : "f"(lo), "f"(hi));
    return r;
}
// fast activations for the LSTM (single-MUFU tanh; sigmoid via exact identity)
__device__ __forceinline__ float tanha(float x) {
    float r;
    asm("tanh.approx.f32 %0, %1;" : "=f"(r) : "f"(x));
    return r;
}
__device__ __forceinline__ float sigma(float x) {
    return fmaf(tanha(0.5f * x), 0.5f, 0.5f);
}

// ---------------------------------------------------------------------------
// Kernel 1: FUSED conv -> relu -> maxpool -> fc1 GEMM, WARP-SPECIALIZED.
// R11 structure + producer-side register PREFETCH of next tile's x/conv
// params (overlaps gmem latency with conv compute).
// ---------------------------------------------------------------------------
__global__ __launch_bounds__(512) void k_convfc(
    const float* __restrict__ x,
    const float* __restrict__ conv_w, const float* __restrict__ conv_b,
    const float* __restrict__ fc1_w,  const float* __restrict__ fc1_b)
{
    extern __shared__ float smf[];
    float* Wfp  = smf;                // 32 x 1044 = 33408
    float* sp   = Wfp + 33408;        // 2 bufs x 8 rows x 1044 = 16704
    float* part = sp + 16704;         // 8c x 8r x 32o = 2048
    float* xr   = part + 2048;        // 8 x 132 = 1056
    float* cw   = xr + 1056;          // 384
    float* cb   = cw + 384;           // 128
    float* fb   = cb + 128;           // 32
    // total 53760 floats = 215,040 B

    const int tid = threadIdx.x;
    const int b   = blockIdx.x;

    for (int o = 0; o < 32; ++o)
        for (int c = tid; c < 1040; c += 512)
            Wfp[o * 1044 + c] = fc1_w[o * 1040 + c];
    if (tid < 32) fb[tid] = fc1_b[tid];
    __syncthreads();

    if (tid >= 256) {
        // ---------------- PRODUCER: stage + conv tile p ----------------
        const int ptid = tid - 256;
        const int crow = ptid >> 5;
        const int ck   = (ptid >> 1) & 15;
        const int chal = ptid & 1;
        const int srow = ptid >> 5;
        const int sc4  = (ptid & 31) * 4;

        const int j0    = chal ? 33 : 0;
        const int iters = chal ? 32 : 33;

        // prefetch tile 0 into registers
        float4 vx = *(const float4*)(x + (size_t)b * 16384 + srow * 128 + sc4);
        float  vcw0 = conv_w[ptid];               // i = ptid
        float  vcw1 = (ptid + 256 < 384) ? conv_w[ptid + 256] : 0.0f;
        float  vcb  = (ptid < 128) ? conv_b[ptid] : 0.0f;

        for (int p = 0; p <= 16; ++p) {
            if (p < 16) {
                const int w0 = p * 8;
                float* spb = sp + (p & 1) * 8352;

                // store prefetched tile-p data to smem
                {
                    float* xd = xr + srow * 132 + 1 + sc4;
                    xd[0] = vx.x; xd[1] = vx.y; xd[2] = vx.z; xd[3] = vx.w;
                }
                if (ptid < 8) { xr[ptid * 132] = 0.0f; xr[ptid * 132 + 129] = 0.0f; }
                cw[ptid] = vcw0;
                if (ptid + 256 < 384) cw[ptid + 256] = vcw1;
                if (ptid < 128) cb[ptid] = vcb;

                // prefetch tile p+1 (overlaps with conv below)
                if (p + 1 < 16) {
                    const int w1 = (p + 1) * 8;
                    vx   = *(const float4*)(x + (size_t)b * 16384
                                            + (w1 + srow) * 128 + sc4);
                    vcw0 = conv_w[w1 * 48 + ptid];
                    vcw1 = (ptid + 256 < 384) ? conv_w[w1 * 48 + ptid + 256] : 0.0f;
                    vcb  = (ptid < 128) ? conv_b[w1 * 16 + ptid] : 0.0f;
                }
                asm volatile("bar.sync 1, 256;" ::: "memory");

                // conv + relu + maxpool: rolling-register window, 1 LDS.64/j
                {
                    const float c0w = cw[crow * 48 + ck * 3];
                    const float c1w = cw[crow * 48 + ck * 3 + 1];
                    const float c2w = cw[crow * 48 + ck * 3 + 2];
                    const float bb  = cb[crow * 16 + ck];
                    const float* xp = xr + crow * 132;
                    float* pp = spb + crow * 1044 + ck * 65;

                    float2 Pj  = *(const float2*)(xp + 2 * j0);
                    float  pm1 = chal ? xp[2 * j0 - 1] : 0.0f;
                    for (int it = 0; it < iters; ++it) {
                        const int j = j0 + it;
                        const int pq = 2 * j;
                        float2 Pn = *(const float2*)(xp + pq + 2);
                        float va = -1e30f, vb = -1e30f;
                        if (pq > 0)
                            va = fmaxf(0.0f, bb + c0w * pm1 + c1w * Pj.x + c2w * Pj.y);
                        if (pq < 128)
                            vb = fmaxf(0.0f, bb + c0w * Pj.x + c1w * Pj.y + c2w * Pn.x);
                        pp[j] = fmaxf(va, vb);
                        pm1 = Pj.y;
                        Pj  = Pn;
                    }
                }
            }
            __syncthreads();
        }
    } else {
        // ---------------- CONSUMER: GEMM + combine tile p-1 ----------------
        const int wid  = tid >> 5, lane = tid & 31;
        const int qn   = (wid < 4) ? 33 : 32;
        const int qb   = (wid < 4) ? wid * 33 : 132 + (wid - 4) * 32;
        const int rr   = tid >> 5;
        const int oo   = tid & 31;

        for (int p = 0; p <= 16; ++p) {
            if (p >= 1) {
                const int w0 = (p - 1) * 8;
                const float* spb = sp + ((p - 1) & 1) * 8352;

                {
                    const ulonglong2* wrow = (const ulonglong2*)(Wfp + lane * 1044) + qb;
                    ull acc[8] = {0, 0, 0, 0, 0, 0, 0, 0};
                    #pragma unroll 3
                    for (int q = 0; q < qn; ++q) {
                        ulonglong2 wv = wrow[q];
                        #pragma unroll
                        for (int r = 0; r < 8; ++r) {
                            ulonglong2 hv =
                                ((const ulonglong2*)(spb + r * 1044))[qb + q];
                            ffma2(acc[r], hv.x, wv.x);
                            ffma2(acc[r], hv.y, wv.y);
                        }
                    }
                    #pragma unroll
                    for (int r = 0; r < 8; ++r)
                        part[(wid * 8 + r) * 32 + lane] = redu(acc[r]);
                }
                asm volatile("bar.sync 2, 256;" ::: "memory");

                {
                    float s = fb[oo];
                    #pragma unroll
                    for (int c = 0; c < 8; ++c)
                        s += part[(c * 8 + rr) * 32 + oo];
                    g_z[oo * 16384 + b * 128 + w0 + rr] = s;
                }
            }
            __syncthreads();
        }
    }
}

// ---------------------------------------------------------------------------
// Kernel 2: the LSTM. R12 structure + layer-0 weights FULLY register-resident
// (V0..V3): zero W0 smem reads inside the 128-step loop.
// ---------------------------------------------------------------------------
__global__ __launch_bounds__(256, 1) void k_lstm(
    const float* __restrict__ w_ih0, const float* __restrict__ w_ih1,
    const float* __restrict__ w_hh,  const float* __restrict__ b_lstm)
{
    extern __shared__ ull sm2[];
    ulonglong2* W0q = (ulonglong2*)sm2;            // [8 hp2][128 g]   16KB (init only)
    ulonglong2* Wcq = (ulonglong2*)(sm2 + 2048);   // [16 hp2][128 g]  32KB
    ull*   hcat = sm2 + 6144;                      // [32 cells][32 pairs] 8KB
    float* zb   = (float*)(sm2 + 7168);            // [32 b][128 t]    16KB
    float* wi0  = zb + 4096;                       // 128
    float* bs0  = wi0 + 128;                       // 128
    float* bs1  = bs0 + 128;                       // 128

    const int tid = threadIdx.x;
    const int f   = blockIdx.x & 31;
    const int b0  = (blockIdx.x >> 5) * 32;

    const float* whh0 = w_hh  + (size_t)f        * 4096;  // [g][h]
    const float* whh1 = w_hh  + (size_t)(32 + f) * 4096;
    const float* wi1  = w_ih1 + (size_t)f        * 4096;

    for (int idx = tid; idx < 1024; idx += 256) {
        int hp2 = idx >> 7, gg = idx & 127;
        float4 v = *(const float4*)(whh0 + gg * 32 + 4 * hp2);
        W0q[idx] = make_ulonglong2(pk2(v.x, v.y), pk2(v.z, v.w));
    }
    for (int idx = tid; idx < 2048; idx += 256) {
        int hp2 = idx >> 7, gg = idx & 127;
        float4 v = (hp2 < 8) ? *(const float4*)(wi1  + gg * 32 + 4 * hp2)
                             : *(const float4*)(whh1 + gg * 32 + 4 * (hp2 - 8));
        Wcq[idx] = make_ulonglong2(pk2(v.x, v.y), pk2(v.z, v.w));
    }
    if (tid < 128) {
        wi0[tid] = w_ih0[f * 128 + tid];
        bs0[tid] = b_lstm[f * 128 + tid];
        bs1[tid] = b_lstm[(32 + f) * 128 + tid];
    }
    for (int idx = tid; idx < 4096; idx += 256)
        zb[idx] = g_z[f * 16384 + b0 * 128 + idx];
    for (int idx = tid; idx < 1024; idx += 256) hcat[idx] = 0ull;
    __syncthreads();

    const int wg = tid >> 5, lane = tid & 31;
    ull* hbase = hcat + (wg * 4) * 32;             // 4 cells x 32 pairs

    float wi0g[4], bs0g[4], bs1g[4];
    #pragma unroll
    for (int gg = 0; gg < 4; ++gg) {
        wi0g[gg] = wi0[lane + 32 * gg];
        bs0g[gg] = bs0[lane + 32 * gg];
        bs1g[gg] = bs1[lane + 32 * gg];
    }

    // layer0 weights: ALL FOUR gate-groups held in registers (loop-invariant)
    ulonglong2 V0[8], V1[8], V2[8], V3[8];
    #pragma unroll
    for (int hp2 = 0; hp2 < 8; ++hp2) {
        V0[hp2] = W0q[hp2 * 128 + lane];
        V1[hp2] = W0q[hp2 * 128 + lane + 32];
        V2[hp2] = W0q[hp2 * 128 + lane + 64];
        V3[hp2] = W0q[hp2 * 128 + lane + 96];
    }

    float c0[4] = {0, 0, 0, 0};
    float c1[4] = {0, 0, 0, 0};
    float h1v[4];
    const float* zw = zb + (wg * 4) * 128;

    // prologue: gates0(t=0) = x(0)*wi0 + b0  (h0(-1)=0)
    ull a0[4][4];
    #pragma unroll
    for (int r = 0; r < 4; ++r) {
        float xv = zw[r * 128];
        #pragma unroll
        for (int gg = 0; gg < 4; ++gg)
            a0[r][gg] = pk2(fmaf(xv, wi0g[gg], bs0g[gg]), 0.0f);
    }

    #pragma unroll 2
    for (int t = 0; t < 128; ++t) {
        // ---- (1) a1 partial: bias + contraction over h1(t-1) (hp2 8..15) ----
        ull a1[4][4];
        #pragma unroll
        for (int r = 0; r < 4; ++r)
            #pragma unroll
            for (int gg = 0; gg < 4; ++gg)
                a1[r][gg] = pk2(bs1g[gg], 0.0f);
        #pragma unroll
        for (int hp2 = 8; hp2 < 16; ++hp2) {
            ulonglong2 u0 = Wcq[hp2 * 128 + lane];
            ulonglong2 u1 = Wcq[hp2 * 128 + lane + 32];
            ulonglong2 u2 = Wcq[hp2 * 128 + lane + 64];
            ulonglong2 u3 = Wcq[hp2 * 128 + lane + 96];
            #pragma unroll
            for (int r = 0; r < 4; ++r) {
                ulonglong2 hv = ((const ulonglong2*)(hbase + r * 32))[hp2];
                ffma2(a1[r][0], hv.x, u0.x); ffma2(a1[r][0], hv.y, u0.y);
                ffma2(a1[r][1], hv.x, u1.x); ffma2(a1[r][1], hv.y, u1.y);
                ffma2(a1[r][2], hv.x, u2.x); ffma2(a1[r][2], hv.y, u2.y);
                ffma2(a1[r][3], hv.x, u3.x); ffma2(a1[r][3], hv.y, u3.y);
            }
        }

        // ---- (2) A0: h0(t) from a0 ----
        #pragma unroll
        for (int r = 0; r < 4; ++r) {
            float gi  = redu(a0[r][0]);
            float gf  = redu(a0[r][1]);
            float gg_ = redu(a0[r][2]);
            float go  = redu(a0[r][3]);
            c0[r] = sigma(gf) * c0[r] + sigma(gi) * tanha(gg_);
            ((float*)(hbase + r * 32))[lane] = sigma(go) * tanha(c0[r]);
        }
        __syncwarp();

        // ---- (3) shared-h0 GEMM: finish a1, start a0(t+1) ----
        {
            const int tn = (t + 1) & 127;
            #pragma unroll
            for (int r = 0; r < 4; ++r) {
                float xv = zw[r * 128 + tn];
                #pragma unroll
                for (int gg = 0; gg < 4; ++gg)
                    a0[r][gg] = pk2(fmaf(xv, wi0g[gg], bs0g[gg]), 0.0f);
            }
        }
        #pragma unroll
        for (int hp2 = 0; hp2 < 8; ++hp2) {
            ulonglong2 u0 = Wcq[hp2 * 128 + lane];
            ulonglong2 u1 = Wcq[hp2 * 128 + lane + 32];
            ulonglong2 u2 = Wcq[hp2 * 128 + lane + 64];
            ulonglong2 u3 = Wcq[hp2 * 128 + lane + 96];
            #pragma unroll
            for (int r = 0; r < 4; ++r) {
                ulonglong2 hv = ((const ulonglong2*)(hbase + r * 32))[hp2];
                ffma2(a1[r][0], hv.x, u0.x); ffma2(a1[r][0], hv.y, u0.y);
                ffma2(a1[r][1], hv.x, u1.x); ffma2(a1[r][1], hv.y, u1.y);
                ffma2(a1[r][2], hv.x, u2.x); ffma2(a1[r][2], hv.y, u2.y);
                ffma2(a1[r][3], hv.x, u3.x); ffma2(a1[r][3], hv.y, u3.y);
                ffma2(a0[r][0], hv.x, V0[hp2].x); ffma2(a0[r][0], hv.y, V0[hp2].y);
                ffma2(a0[r][1], hv.x, V1[hp2].x); ffma2(a0[r][1], hv.y, V1[hp2].y);
                ffma2(a0[r][2], hv.x, V2[hp2].x); ffma2(a0[r][2], hv.y, V2[hp2].y);
                ffma2(a0[r][3], hv.x, V3[hp2].x); ffma2(a0[r][3], hv.y, V3[hp2].y);
            }
        }

        // ---- (4) A1: h1(t) from a1 ----
        #pragma unroll
        for (int r = 0; r < 4; ++r) {
            float gi  = redu(a1[r][0]);
            float gf  = redu(a1[r][1]);
            float gg_ = redu(a1[r][2]);
            float go  = redu(a1[r][3]);
            c1[r]  = sigma(gf) * c1[r] + sigma(gi) * tanha(gg_);
            h1v[r] = sigma(go) * tanha(c1[r]);
            ((float*)(hbase + r * 32))[32 + lane] = h1v[r];
        }
        __syncwarp();
    }

    #pragma unroll
    for (int r = 0; r < 4; ++r)
        g_comb[(size_t)(b0 + wg * 4 + r) * 1024 + f * 32 + lane] = h1v[r];
}

// ---------------------------------------------------------------------------
// Kernel 3: gaussian head. Block per b, 256 threads, float4 loads.
// ---------------------------------------------------------------------------
__global__ __launch_bounds__(256) void k_head(
    const float* __restrict__ mu_w, const float* __restrict__ mu_b,
    const float* __restrict__ lv_w, const float* __restrict__ lv_b,
    float* __restrict__ out)
{
    __shared__ float smu[8], slv[8];
    const int tid = threadIdx.x, b = blockIdx.x;

    float4 v  = ((const float4*)(g_comb + (size_t)b * 1024))[tid];
    float4 mw = ((const float4*)mu_w)[tid];
    float4 lw = ((const float4*)lv_w)[tid];
    float am = v.x * mw.x + v.y * mw.y + v.z * mw.z + v.w * mw.w;
    float al = v.x * lw.x + v.y * lw.y + v.z * lw.z + v.w * lw.w;

    #pragma unroll
    for (int s = 16; s > 0; s >>= 1) {
        am += __shfl_xor_sync(0xffffffffu, am, s);
        al += __shfl_xor_sync(0xffffffffu, al, s);
    }
    const int wg = tid >> 5, lane = tid & 31;
    if (lane == 0) { smu[wg] = am; slv[wg] = al; }
    __syncthreads();
    if (tid == 0) {
        float mu = mu_b[0], lv = lv_b[0];
        #pragma unroll
        for (int i = 0; i < 8; ++i) { mu += smu[i]; lv += slv[i]; }
        float sg = expf(0.5f * lv);
        out[b]       = mu - 1.96f * sg;
        out[128 + b] = mu;
        out[256 + b] = mu + 1.96f * sg;
        out[384 + b] = lv;
    }
}

// ---------------------------------------------------------------------------
extern "C" void kernel_launch(void* const* d_in, const int* in_sizes, int n_in,
                              void* d_out, int out_size)
{
    const float* x      = (const float*)d_in[0];
    const float* conv_w = (const float*)d_in[1];
    const float* conv_b = (const float*)d_in[2];
    const float* fc1_w  = (const float*)d_in[3];
    const float* fc1_b  = (const float*)d_in[4];
    const float* w_ih0  = (const float*)d_in[5];
    const float* w_ih1  = (const float*)d_in[6];
    const float* w_hh   = (const float*)d_in[7];
    const float* b_lstm = (const float*)d_in[8];
    const float* mu_w   = (const float*)d_in[9];
    const float* mu_b   = (const float*)d_in[10];
    const float* lv_w   = (const float*)d_in[11];
    const float* lv_b   = (const float*)d_in[12];
    float* out = (float*)d_out;

    const int SM_CF   = 53760 * (int)sizeof(float);                        // 215,040 B
    const int SM_LSTM = 9408 * (int)sizeof(ull);                           //  75,264 B

    cudaFuncSetAttribute(k_convfc, cudaFuncAttributeMaxDynamicSharedMemorySize, SM_CF);
    cudaFuncSetAttribute(k_lstm,   cudaFuncAttributeMaxDynamicSharedMemorySize, SM_LSTM);

    k_convfc<<<128, 512, SM_CF>>>(x, conv_w, conv_b, fc1_w, fc1_b);
    k_lstm<<<128, 256, SM_LSTM>>>(w_ih0, w_ih1, w_hh, b_lstm);
    k_head<<<128, 256>>>(mu_w, mu_b, lv_w, lv_b, out);
}

// round 15
// speedup vs baseline: 1.0426x; 1.0426x over previous
#include <cuda_runtime.h>

// ---------------------------------------------------------------------------
// Groupwise CNN + 32 independent 2-layer LSTMs + gaussian head
// ---------------------------------------------------------------------------

typedef unsigned long long ull;

#define B_    128
#define W_    128
#define FC1_  32
#define H_    32

// scratch (allocation-free rule: __device__ globals)
__device__ float g_z[FC1_ * 16384];          // [f][b*128+t]  (transposed for lstm)
__device__ float g_comb[B_ * FC1_ * H_];     // [b][f*32+h]

__device__ __forceinline__ void ffma2(ull &d, ull a, ull b) {
    asm("fma.rn.f32x2 %0, %1, %2, %0;" : "+l"(d) : "l"(a), "l"(b));
}
__device__ __forceinline__ float redu(ull a) {
    float lo, hi;
    asm("mov.b64 {%0,%1}, %2;" : "=f"(lo), "=f"(hi) : "l"(a));
    return lo + hi;
}
__device__ __forceinline__ ull pk2(float lo, float hi) {
    ull r;
    asm("mov.b64 %0, {%1,%2};" : "=l"(r) : "f"(lo), "f"(hi));
    return r;
}
// fast activations for the LSTM (single-MUFU tanh)
__device__ __forceinline__ float tanha(float x) {
    float r;
    asm("tanh.approx.f32 %0, %1;" : "=f"(r) : "f"(x));
    return r;
}
// sigmoid on a PRE-HALVED gate: weights/biases of i,f,o gates are scaled by
// 0.5 at staging time, so sigma(2g) = 0.5*tanh(g) + 0.5 needs no multiply.
__device__ __forceinline__ float sigp(float g) {
    return fmaf(tanha(g), 0.5f, 0.5f);
}

// ---------------------------------------------------------------------------
// Kernel 1: FUSED conv -> relu -> maxpool -> fc1 GEMM, WARP-SPECIALIZED.
// (frozen at R11/R12 best — no prefetch, it was neutral-negative)
// ---------------------------------------------------------------------------
__global__ __launch_bounds__(512) void k_convfc(
    const float* __restrict__ x,
    const float* __restrict__ conv_w, const float* __restrict__ conv_b,
    const float* __restrict__ fc1_w,  const float* __restrict__ fc1_b)
{
    extern __shared__ float smf[];
    float* Wfp  = smf;                // 32 x 1044 = 33408
    float* sp   = Wfp + 33408;        // 2 bufs x 8 rows x 1044 = 16704
    float* part = sp + 16704;         // 8c x 8r x 32o = 2048
    float* xr   = part + 2048;        // 8 x 132 = 1056
    float* cw   = xr + 1056;          // 384
    float* cb   = cw + 384;           // 128
    float* fb   = cb + 128;           // 32
    // total 53760 floats = 215,040 B

    const int tid = threadIdx.x;
    const int b   = blockIdx.x;

    for (int o = 0; o < 32; ++o)
        for (int c = tid; c < 1040; c += 512)
            Wfp[o * 1044 + c] = fc1_w[o * 1040 + c];
    if (tid < 32) fb[tid] = fc1_b[tid];
    __syncthreads();

    if (tid >= 256) {
        // ---------------- PRODUCER: stage + conv tile p ----------------
        const int ptid = tid - 256;
        const int crow = ptid >> 5;
        const int ck   = (ptid >> 1) & 15;
        const int chal = ptid & 1;
        const int srow = ptid >> 5;
        const int sc4  = (ptid & 31) * 4;

        const int j0    = chal ? 33 : 0;
        const int iters = chal ? 32 : 33;

        for (int p = 0; p <= 16; ++p) {
            if (p < 16) {
                const int w0 = p * 8;
                float* spb = sp + (p & 1) * 8352;

                {
                    float4 v = *(const float4*)(x + (size_t)b * 16384
                                                + (w0 + srow) * 128 + sc4);
                    float* xd = xr + srow * 132 + 1 + sc4;
                    xd[0] = v.x; xd[1] = v.y; xd[2] = v.z; xd[3] = v.w;
                }
                if (ptid < 8) { xr[ptid * 132] = 0.0f; xr[ptid * 132 + 129] = 0.0f; }
                for (int i = ptid; i < 384; i += 256) cw[i] = conv_w[w0 * 48 + i];
                if (ptid < 128) cb[ptid] = conv_b[w0 * 16 + ptid];
                asm volatile("bar.sync 1, 256;" ::: "memory");

                {
                    const float c0w = cw[crow * 48 + ck * 3];
                    const float c1w = cw[crow * 48 + ck * 3 + 1];
                    const float c2w = cw[crow * 48 + ck * 3 + 2];
                    const float bb  = cb[crow * 16 + ck];
                    const float* xp = xr + crow * 132;
                    float* pp = spb + crow * 1044 + ck * 65;

                    float2 Pj  = *(const float2*)(xp + 2 * j0);
                    float  pm1 = chal ? xp[2 * j0 - 1] : 0.0f;
                    for (int it = 0; it < iters; ++it) {
                        const int j = j0 + it;
                        const int pq = 2 * j;
                        float2 Pn = *(const float2*)(xp + pq + 2);
                        float va = -1e30f, vb = -1e30f;
                        if (pq > 0)
                            va = fmaxf(0.0f, bb + c0w * pm1 + c1w * Pj.x + c2w * Pj.y);
                        if (pq < 128)
                            vb = fmaxf(0.0f, bb + c0w * Pj.x + c1w * Pj.y + c2w * Pn.x);
                        pp[j] = fmaxf(va, vb);
                        pm1 = Pj.y;
                        Pj  = Pn;
                    }
                }
            }
            __syncthreads();
        }
    } else {
        // ---------------- CONSUMER: GEMM + combine tile p-1 ----------------
        const int wid  = tid >> 5, lane = tid & 31;
        const int qn   = (wid < 4) ? 33 : 32;
        const int qb   = (wid < 4) ? wid * 33 : 132 + (wid - 4) * 32;
        const int rr   = tid >> 5;
        const int oo   = tid & 31;

        for (int p = 0; p <= 16; ++p) {
            if (p >= 1) {
                const int w0 = (p - 1) * 8;
                const float* spb = sp + ((p - 1) & 1) * 8352;

                {
                    const ulonglong2* wrow = (const ulonglong2*)(Wfp + lane * 1044) + qb;
                    ull acc[8] = {0, 0, 0, 0, 0, 0, 0, 0};
                    #pragma unroll 3
                    for (int q = 0; q < qn; ++q) {
                        ulonglong2 wv = wrow[q];
                        #pragma unroll
                        for (int r = 0; r < 8; ++r) {
                            ulonglong2 hv =
                                ((const ulonglong2*)(spb + r * 1044))[qb + q];
                            ffma2(acc[r], hv.x, wv.x);
                            ffma2(acc[r], hv.y, wv.y);
                        }
                    }
                    #pragma unroll
                    for (int r = 0; r < 8; ++r)
                        part[(wid * 8 + r) * 32 + lane] = redu(acc[r]);
                }
                asm volatile("bar.sync 2, 256;" ::: "memory");

                {
                    float s = fb[oo];
                    #pragma unroll
                    for (int c = 0; c < 8; ++c)
                        s += part[(c * 8 + rr) * 32 + oo];
                    g_z[oo * 16384 + b * 128 + w0 + rr] = s;
                }
            }
            __syncthreads();
        }
    }
}

// ---------------------------------------------------------------------------
// Kernel 2: the LSTM. R12 structure (V0/V1 register-resident only) with
// i/f/o gate weights+biases PRE-SCALED by 0.5 at staging: sigmoid becomes
// fmaf(tanh(g),0.5,0.5) with no in-loop multiply (exact algebraic fold).
// ---------------------------------------------------------------------------
__global__ __launch_bounds__(256, 1) void k_lstm(
    const float* __restrict__ w_ih0, const float* __restrict__ w_ih1,
    const float* __restrict__ w_hh,  const float* __restrict__ b_lstm)
{
    extern __shared__ ull sm2[];
    ulonglong2* W0q = (ulonglong2*)sm2;            // [8 hp2][128 g]   16KB
    ulonglong2* Wcq = (ulonglong2*)(sm2 + 2048);   // [16 hp2][128 g]  32KB
    ull*   hcat = sm2 + 6144;                      // [32 cells][32 pairs] 8KB
    float* zb   = (float*)(sm2 + 7168);            // [32 b][128 t]    16KB
    float* wi0  = zb + 4096;                       // 128
    float* bs0  = wi0 + 128;                       // 128
    float* bs1  = bs0 + 128;                       // 128

    const int tid = threadIdx.x;
    const int f   = blockIdx.x & 31;
    const int b0  = (blockIdx.x >> 5) * 32;

    const float* whh0 = w_hh  + (size_t)f        * 4096;  // [g][h]
    const float* whh1 = w_hh  + (size_t)(32 + f) * 4096;
    const float* wi1  = w_ih1 + (size_t)f        * 4096;

    // gate scale: groups 0(i),1(f),3(o) pre-halved; group 2(g) untouched
    for (int idx = tid; idx < 1024; idx += 256) {
        int hp2 = idx >> 7, gg = idx & 127;
        float s = ((gg >> 5) == 2) ? 1.0f : 0.5f;
        float4 v = *(const float4*)(whh0 + gg * 32 + 4 * hp2);
        W0q[idx] = make_ulonglong2(pk2(s * v.x, s * v.y), pk2(s * v.z, s * v.w));
    }
    for (int idx = tid; idx < 2048; idx += 256) {
        int hp2 = idx >> 7, gg = idx & 127;
        float s = ((gg >> 5) == 2) ? 1.0f : 0.5f;
        float4 v = (hp2 < 8) ? *(const float4*)(wi1  + gg * 32 + 4 * hp2)
                             : *(const float4*)(whh1 + gg * 32 + 4 * (hp2 - 8));
        Wcq[idx] = make_ulonglong2(pk2(s * v.x, s * v.y), pk2(s * v.z, s * v.w));
    }
    if (tid < 128) {
        float s = ((tid >> 5) == 2) ? 1.0f : 0.5f;
        wi0[tid] = s * w_ih0[f * 128 + tid];
        bs0[tid] = s * b_lstm[f * 128 + tid];
        bs1[tid] = s * b_lstm[(32 + f) * 128 + tid];
    }
    for (int idx = tid; idx < 4096; idx += 256)
        zb[idx] = g_z[f * 16384 + b0 * 128 + idx];
    for (int idx = tid; idx < 1024; idx += 256) hcat[idx] = 0ull;
    __syncthreads();

    const int wg = tid >> 5, lane = tid & 31;
    ull* hbase = hcat + (wg * 4) * 32;             // 4 cells x 32 pairs

    float wi0g[4], bs0g[4], bs1g[4];
    #pragma unroll
    for (int gg = 0; gg < 4; ++gg) {
        wi0g[gg] = wi0[lane + 32 * gg];
        bs0g[gg] = bs0[lane + 32 * gg];
        bs1g[gg] = bs1[lane + 32 * gg];
    }

    // layer0 weights for gate groups 0,1 held in registers (loop-invariant)
    ulonglong2 V0[8], V1[8];
    #pragma unroll
    for (int hp2 = 0; hp2 < 8; ++hp2) {
        V0[hp2] = W0q[hp2 * 128 + lane];
        V1[hp2] = W0q[hp2 * 128 + lane + 32];
    }

    float c0[4] = {0, 0, 0, 0};
    float c1[4] = {0, 0, 0, 0};
    float h1v[4];
    const float* zw = zb + (wg * 4) * 128;

    // prologue: gates0(t=0) = x(0)*wi0 + b0  (h0(-1)=0)
    ull a0[4][4];
    #pragma unroll
    for (int r = 0; r < 4; ++r) {
        float xv = zw[r * 128];
        #pragma unroll
        for (int gg = 0; gg < 4; ++gg)
            a0[r][gg] = pk2(fmaf(xv, wi0g[gg], bs0g[gg]), 0.0f);
    }

    #pragma unroll 2
    for (int t = 0; t < 128; ++t) {
        // ---- (1) a1 partial: bias + contraction over h1(t-1) (hp2 8..15) ----
        ull a1[4][4];
        #pragma unroll
        for (int r = 0; r < 4; ++r)
            #pragma unroll
            for (int gg = 0; gg < 4; ++gg)
                a1[r][gg] = pk2(bs1g[gg], 0.0f);
        #pragma unroll
        for (int hp2 = 8; hp2 < 16; ++hp2) {
            ulonglong2 u0 = Wcq[hp2 * 128 + lane];
            ulonglong2 u1 = Wcq[hp2 * 128 + lane + 32];
            ulonglong2 u2 = Wcq[hp2 * 128 + lane + 64];
            ulonglong2 u3 = Wcq[hp2 * 128 + lane + 96];
            #pragma unroll
            for (int r = 0; r < 4; ++r) {
                ulonglong2 hv = ((const ulonglong2*)(hbase + r * 32))[hp2];
                ffma2(a1[r][0], hv.x, u0.x); ffma2(a1[r][0], hv.y, u0.y);
                ffma2(a1[r][1], hv.x, u1.x); ffma2(a1[r][1], hv.y, u1.y);
                ffma2(a1[r][2], hv.x, u2.x); ffma2(a1[r][2], hv.y, u2.y);
                ffma2(a1[r][3], hv.x, u3.x); ffma2(a1[r][3], hv.y, u3.y);
            }
        }

        // ---- (2) A0: h0(t) from a0 ----
        #pragma unroll
        for (int r = 0; r < 4; ++r) {
            float gi  = redu(a0[r][0]);
            float gf  = redu(a0[r][1]);
            float gg_ = redu(a0[r][2]);
            float go  = redu(a0[r][3]);
            c0[r] = sigp(gf) * c0[r] + sigp(gi) * tanha(gg_);
            ((float*)(hbase + r * 32))[lane] = sigp(go) * tanha(c0[r]);
        }
        __syncwarp();

        // ---- (3) shared-h0 GEMM: finish a1, start a0(t+1) ----
        {
            const int tn = (t + 1) & 127;
            #pragma unroll
            for (int r = 0; r < 4; ++r) {
                float xv = zw[r * 128 + tn];
                #pragma unroll
                for (int gg = 0; gg < 4; ++gg)
                    a0[r][gg] = pk2(fmaf(xv, wi0g[gg], bs0g[gg]), 0.0f);
            }
        }
        #pragma unroll
        for (int hp2 = 0; hp2 < 8; ++hp2) {
            ulonglong2 u0 = Wcq[hp2 * 128 + lane];
            ulonglong2 u1 = Wcq[hp2 * 128 + lane + 32];
            ulonglong2 u2 = Wcq[hp2 * 128 + lane + 64];
            ulonglong2 u3 = Wcq[hp2 * 128 + lane + 96];
            ulonglong2 v2 = W0q[hp2 * 128 + lane + 64];
            ulonglong2 v3 = W0q[hp2 * 128 + lane + 96];
            #pragma unroll
            for (int r = 0; r < 4; ++r) {
                ulonglong2 hv = ((const ulonglong2*)(hbase + r * 32))[hp2];
                ffma2(a1[r][0], hv.x, u0.x); ffma2(a1[r][0], hv.y, u0.y);
                ffma2(a1[r][1], hv.x, u1.x); ffma2(a1[r][1], hv.y, u1.y);
                ffma2(a1[r][2], hv.x, u2.x); ffma2(a1[r][2], hv.y, u2.y);
                ffma2(a1[r][3], hv.x, u3.x); ffma2(a1[r][3], hv.y, u3.y);
                ffma2(a0[r][0], hv.x, V0[hp2].x); ffma2(a0[r][0], hv.y, V0[hp2].y);
                ffma2(a0[r][1], hv.x, V1[hp2].x); ffma2(a0[r][1], hv.y, V1[hp2].y);
                ffma2(a0[r][2], hv.x, v2.x); ffma2(a0[r][2], hv.y, v2.y);
                ffma2(a0[r][3], hv.x, v3.x); ffma2(a0[r][3], hv.y, v3.y);
            }
        }

        // ---- (4) A1: h1(t) from a1 ----
        #pragma unroll
        for (int r = 0; r < 4; ++r) {
            float gi  = redu(a1[r][0]);
            float gf  = redu(a1[r][1]);
            float gg_ = redu(a1[r][2]);
            float go  = redu(a1[r][3]);
            c1[r]  = sigp(gf) * c1[r] + sigp(gi) * tanha(gg_);
            h1v[r] = sigp(go) * tanha(c1[r]);
            ((float*)(hbase + r * 32))[32 + lane] = h1v[r];
        }
        __syncwarp();
    }

    #pragma unroll
    for (int r = 0; r < 4; ++r)
        g_comb[(size_t)(b0 + wg * 4 + r) * 1024 + f * 32 + lane] = h1v[r];
}

// ---------------------------------------------------------------------------
// Kernel 3: gaussian head. Block per b, 256 threads, float4 loads.
// ---------------------------------------------------------------------------
__global__ __launch_bounds__(256) void k_head(
    const float* __restrict__ mu_w, const float* __restrict__ mu_b,
    const float* __restrict__ lv_w, const float* __restrict__ lv_b,
    float* __restrict__ out)
{
    __shared__ float smu[8], slv[8];
    const int tid = threadIdx.x, b = blockIdx.x;

    float4 v  = ((const float4*)(g_comb + (size_t)b * 1024))[tid];
    float4 mw = ((const float4*)mu_w)[tid];
    float4 lw = ((const float4*)lv_w)[tid];
    float am = v.x * mw.x + v.y * mw.y + v.z * mw.z + v.w * mw.w;
    float al = v.x * lw.x + v.y * lw.y + v.z * lw.z + v.w * lw.w;

    #pragma unroll
    for (int s = 16; s > 0; s >>= 1) {
        am += __shfl_xor_sync(0xffffffffu, am, s);
        al += __shfl_xor_sync(0xffffffffu, al, s);
    }
    const int wg = tid >> 5, lane = tid & 31;
    if (lane == 0) { smu[wg] = am; slv[wg] = al; }
    __syncthreads();
    if (tid == 0) {
        float mu = mu_b[0], lv = lv_b[0];
        #pragma unroll
        for (int i = 0; i < 8; ++i) { mu += smu[i]; lv += slv[i]; }
        float sg = expf(0.5f * lv);
        out[b]       = mu - 1.96f * sg;
        out[128 + b] = mu;
        out[256 + b] = mu + 1.96f * sg;
        out[384 + b] = lv;
    }
}

// ---------------------------------------------------------------------------
extern "C" void kernel_launch(void* const* d_in, const int* in_sizes, int n_in,
                              void* d_out, int out_size)
{
    const float* x      = (const float*)d_in[0];
    const float* conv_w = (const float*)d_in[1];
    const float* conv_b = (const float*)d_in[2];
    const float* fc1_w  = (const float*)d_in[3];
    const float* fc1_b  = (const float*)d_in[4];
    const float* w_ih0  = (const float*)d_in[5];
    const float* w_ih1  = (const float*)d_in[6];
    const float* w_hh   = (const float*)d_in[7];
    const float* b_lstm = (const float*)d_in[8];
    const float* mu_w   = (const float*)d_in[9];
    const float* mu_b   = (const float*)d_in[10];
    const float* lv_w   = (const float*)d_in[11];
    const float* lv_b   = (const float*)d_in[12];
    float* out = (float*)d_out;

    const int SM_CF   = 53760 * (int)sizeof(float);                        // 215,040 B
    const int SM_LSTM = 9408 * (int)sizeof(ull);                           //  75,264 B

    cudaFuncSetAttribute(k_convfc, cudaFuncAttributeMaxDynamicSharedMemorySize, SM_CF);
    cudaFuncSetAttribute(k_lstm,   cudaFuncAttributeMaxDynamicSharedMemorySize, SM_LSTM);

    k_convfc<<<128, 512, SM_CF>>>(x, conv_w, conv_b, fc1_w, fc1_b);
    k_lstm<<<128, 256, SM_LSTM>>>(w_ih0, w_ih1, w_hh, b_lstm);
    k_head<<<128, 256>>>(mu_w, mu_b, lv_w, lv_b, out);
}